// round 1
// baseline (speedup 1.0000x reference)
#include <cuda_runtime.h>

// SpatialTransformer (VoxelMorph) trilinear warp, zero padding, align_corners=True.
// src:  [B=2, C=2, D=160, H=192, W=160] f32
// flow: [B=2, 3,   D=160, H=192, W=160] f32  (flow[:,0]=dz, [:,1]=dy, [:,2]=dx)
// out:  [B=2, C=2, D=160, H=192, W=160] f32

namespace {
constexpr int D = 160, H = 192, W = 160, C = 2, B = 2;
constexpr long long N  = (long long)D * H * W;   // 4,915,200
constexpr long long HW = (long long)H * W;
}

__global__ __launch_bounds__(256)
void st_warp_kernel(const float* __restrict__ src,
                    const float* __restrict__ flow,
                    float* __restrict__ out)
{
    long long s = (long long)blockIdx.x * blockDim.x + threadIdx.x;
    if (s >= N) return;
    const int b = blockIdx.y;

    // decode spatial coords (W contiguous)
    const int w = (int)(s % W);
    const int t = (int)(s / W);
    const int h = t % H;
    const int d = t / H;

    const float* fb = flow + (long long)b * 3 * N;
    const float z = (float)d + fb[s];
    const float y = (float)h + fb[s + N];
    const float x = (float)w + fb[s + 2 * N];

    const float z0f = floorf(z), y0f = floorf(y), x0f = floorf(x);
    const float fz = z - z0f, fy = y - y0f, fx = x - x0f;
    const int z0 = (int)z0f, y0 = (int)y0f, x0 = (int)x0f;
    const float gz = 1.0f - fz, gy = 1.0f - fy, gx = 1.0f - fx;

    const float* s0 = src + (long long)b * C * N;   // channel 0
    const float* s1 = s0 + N;                       // channel 1

    float a0 = 0.0f, a1 = 0.0f;

    if (z0 >= 0 && z0 < D - 1 && y0 >= 0 && y0 < H - 1 && x0 >= 0 && x0 < W - 1) {
        // interior fast path: all 8 corners in-bounds
        const long long base = ((long long)z0 * H + y0) * W + x0;
        const float w00 = gz * gy, w01 = gz * fy, w10 = fz * gy, w11 = fz * fy;
        const float w000 = w00 * gx, w001 = w00 * fx;
        const float w010 = w01 * gx, w011 = w01 * fx;
        const float w100 = w10 * gx, w101 = w10 * fx;
        const float w110 = w11 * gx, w111 = w11 * fx;

        const float* p0 = s0 + base;
        const float* p1 = s1 + base;
        a0 = w000 * p0[0]      + w001 * p0[1]
           + w010 * p0[W]      + w011 * p0[W + 1]
           + w100 * p0[HW]     + w101 * p0[HW + 1]
           + w110 * p0[HW + W] + w111 * p0[HW + W + 1];
        a1 = w000 * p1[0]      + w001 * p1[1]
           + w010 * p1[W]      + w011 * p1[W + 1]
           + w100 * p1[HW]     + w101 * p1[HW + 1]
           + w110 * p1[HW + W] + w111 * p1[HW + W + 1];
    } else {
        // boundary path: per-corner validity (zero padding)
        #pragma unroll
        for (int dz = 0; dz < 2; ++dz) {
            const int zi = z0 + dz;
            if ((unsigned)zi >= (unsigned)D) continue;
            const float wz = dz ? fz : gz;
            #pragma unroll
            for (int dy = 0; dy < 2; ++dy) {
                const int yi = y0 + dy;
                if ((unsigned)yi >= (unsigned)H) continue;
                const float wzy = wz * (dy ? fy : gy);
                #pragma unroll
                for (int dx = 0; dx < 2; ++dx) {
                    const int xi = x0 + dx;
                    if ((unsigned)xi >= (unsigned)W) continue;
                    const float wgt = wzy * (dx ? fx : gx);
                    const long long lin = ((long long)zi * H + yi) * W + xi;
                    a0 += wgt * s0[lin];
                    a1 += wgt * s1[lin];
                }
            }
        }
    }

    float* ob = out + (long long)b * C * N;
    ob[s]     = a0;
    ob[s + N] = a1;
}

extern "C" void kernel_launch(void* const* d_in, const int* in_sizes, int n_in,
                              void* d_out, int out_size)
{
    const float* src  = (const float*)d_in[0];
    const float* flow = (const float*)d_in[1];
    float* out = (float*)d_out;

    dim3 block(256);
    dim3 grid((unsigned)((N + 255) / 256), B, 1);
    st_warp_kernel<<<grid, block>>>(src, flow, out);
}